// round 8
// baseline (speedup 1.0000x reference)
#include <cuda_runtime.h>
#include <cstddef>
#include <cstdint>

// ---------------------------------------------------------------------------
// Sparse 3D UNet forward.  cp.async double-buffered sparse-conv GEMM with
// tf32 mma.sync.m16n8k8.  R8: transposed neighbor tables (coalesced, no snbr
// smem), BM=256 with 2 m-tiles/warp (B-fragment reuse across MMAs).
// ---------------------------------------------------------------------------

__device__ float g_pool[224u * 1024u * 1024u];   // 896 MB scratch (static: legal)

__device__ __forceinline__ void cp_async16(uint32_t dst, const void* src, int nbytes) {
    asm volatile("cp.async.cg.shared.global [%0], [%1], 16, %2;"
                 :: "r"(dst), "l"(src), "r"(nbytes));
}
__device__ __forceinline__ void cp_commit() {
    asm volatile("cp.async.commit_group;");
}
template <int NG> __device__ __forceinline__ void cp_wait() {
    asm volatile("cp.async.wait_group %0;" :: "n"(NG));
}
__device__ __forceinline__ uint32_t tf32(float x) {
    uint32_t r; asm("cvt.rna.tf32.f32 %0, %1;" : "=r"(r) : "f"(x)); return r;
}
__device__ __forceinline__ void mma_tf32(float c[4], uint32_t a0, uint32_t a1,
                                         uint32_t a2, uint32_t a3,
                                         uint32_t b0, uint32_t b1) {
    asm volatile(
        "mma.sync.aligned.m16n8k8.row.col.f32.tf32.tf32.f32 "
        "{%0,%1,%2,%3},{%4,%5,%6,%7},{%8,%9},{%0,%1,%2,%3};"
        : "+f"(c[0]), "+f"(c[1]), "+f"(c[2]), "+f"(c[3])
        : "r"(a0), "r"(a1), "r"(a2), "r"(a3), "r"(b0), "r"(b1));
}

// fp32 -> tf32-rounded fp32 bits (grid-stride)
__global__ void cvt_tf32_kernel(const float* __restrict__ in,
                                float* __restrict__ out, int n) {
    for (int i = blockIdx.x * blockDim.x + threadIdx.x; i < n;
         i += gridDim.x * blockDim.x)
        out[i] = __uint_as_float(tf32(in[i]));
}

// nbr[row][k] -> nbrT[k][row] (rows padded to NP with -1).  Coalesced reads.
__global__ void transpose_nbr_kernel(const int* __restrict__ nbr,
                                     int* __restrict__ nbrT, int N, int NP) {
    const long long total = 27LL * NP;
    for (long long i = blockIdx.x * (long long)blockDim.x + threadIdx.x;
         i < total; i += gridDim.x * (long long)blockDim.x) {
        int r = (int)(i / 27), k = (int)(i - 27LL * r);
        nbrT[(size_t)k * NP + r] = (r < N) ? nbr[(size_t)r * 27 + k] : -1;
    }
}

template <int CIN, int COUT>
struct SpCfg {
    static constexpr int BM  = 256;
    static constexpr int MT  = 2;                       // m16 tiles per warp
    static constexpr int CK  = (CIN < 32) ? CIN : 32;
    static constexpr int CK8 = (CK < 8) ? 8 : CK;
    static constexpr int NCH = CIN / CK;
    static constexpr int SP  = CK8 + 4;
    static constexpr int SPW = COUT + 8;
    static constexpr int VR  = CK / 4;
    static constexpr int NT  = COUT / 8;
    static constexpr int KS  = CK8 / 8;
    static constexpr int SMEM_BYTES = (2 * BM * SP + 2 * CK8 * SPW) * 4;
};

template <int CIN, int COUT>
__global__ void __launch_bounds__(256, 2)
spconv_mma(const float* __restrict__ feat, int ldf,   // tf32 input
           const int* __restrict__ nbrT, int NP,      // [27][NP] transposed
           const float* __restrict__ W,               // tf32 (27,CIN,COUT)
           const float* __restrict__ sb,
           const float* __restrict__ resid, int ldr,
           const float* __restrict__ red,   int ldred,
           float* __restrict__ out, int ldo,
           float* __restrict__ outs,                  // tf32 shadow (or null)
           int N)
{
    using C = SpCfg<CIN, COUT>;
    constexpr int BM = C::BM, MT = C::MT, CK = C::CK, CK8 = C::CK8;
    constexpr int NCH = C::NCH, SP = C::SP, SPW = C::SPW, VR = C::VR;
    constexpr int NT = C::NT, KS = C::KS;

    extern __shared__ float smem[];
    float* sfeat = smem;                       // [2][BM*SP]
    float* sW    = smem + 2 * BM * SP;         // [2][CK8*SPW]
    __shared__ int klist[28];
    __shared__ int khit[27];
    __shared__ int knp;

    const uint32_t sfeat_sa = (uint32_t)__cvta_generic_to_shared(sfeat);
    const uint32_t sW_sa    = (uint32_t)__cvta_generic_to_shared(sW);

    const int tid  = threadIdx.x;
    const int lane = tid & 31;
    const int wid  = tid >> 5;                 // 8 warps
    const int row0 = blockIdx.x * BM;

    if (CK8 != CK) {   // zero K-pad region once (CIN=4 layer)
        for (int u = tid; u < 2 * BM * SP + 2 * CK8 * SPW; u += 256) smem[u] = 0.f;
    }

    // khit via coalesced reads of nbrT
    for (int k = wid; k < 27; k += 8) {
        int h = 0;
        const int* col = nbrT + (size_t)k * NP + row0;
        for (int r = lane; r < BM; r += 32) h |= (col[r] >= 0);
        unsigned any = __ballot_sync(0xffffffffu, h);
        if (lane == 0) khit[k] = (any != 0);
    }
    __syncthreads();
    if (tid == 0) {
        int n = 0;
        for (int k = 0; k < 27; ++k) if (khit[k]) klist[n++] = k;
        knp = n;
    }
    __syncthreads();
    const int NS = knp * NCH;

    float acc[MT][NT][4];
#pragma unroll
    for (int m = 0; m < MT; ++m)
#pragma unroll
        for (int t = 0; t < NT; ++t)
#pragma unroll
            for (int j = 0; j < 4; ++j) acc[m][t][j] = 0.f;

    auto stage = [&](int s) {
        const int k  = klist[s / NCH];
        const int ch = s - (s / NCH) * NCH;
        const int kb = s & 1;
        const uint32_t fb = sfeat_sa + (uint32_t)(kb * BM * SP) * 4u;
        {   // one row per thread (BM == 256 == blockDim)
            const int r = tid;
            const int idx = nbrT[(size_t)k * NP + row0 + r];
            const float* g = feat + (size_t)(idx < 0 ? 0 : idx) * ldf + ch * CK;
            const int nb = (idx < 0) ? 0 : 16;
#pragma unroll
            for (int v = 0; v < VR; ++v)
                cp_async16(fb + (uint32_t)(r * SP + v * 4) * 4u, g + v * 4, nb);
        }
        const float* wg = W + ((size_t)k * CIN + (size_t)ch * CK) * COUT;
        const uint32_t wb = sW_sa + (uint32_t)(kb * CK8 * SPW) * 4u;
        for (int u = tid; u < CK * COUT / 4; u += 256) {
            int c = u / (COUT / 4), v = u - c * (COUT / 4);
            cp_async16(wb + (uint32_t)(c * SPW + v * 4) * 4u, wg + c * COUT + v * 4, 16);
        }
    };

    const int mr   = wid * 16 + (lane >> 2);   // m-tile row (tile 0)
    const int kq   = lane & 3;
    const int nq   = lane >> 2;

    if (NS > 0) {
        stage(0);
        cp_commit();
        for (int s = 0; s < NS; ++s) {
            if (s + 1 < NS) { stage(s + 1); cp_commit(); cp_wait<1>(); }
            else            { cp_wait<0>(); }
            __syncthreads();

            const float* fb = sfeat + (s & 1) * BM * SP;
            const float* wb = sW    + (s & 1) * CK8 * SPW;
#pragma unroll
            for (int k8 = 0; k8 < KS; ++k8) {
                const int kc = k8 * 8;
                uint32_t a[MT][4];
#pragma unroll
                for (int m = 0; m < MT; ++m) {
                    const float* fr0 = fb + (mr + m * 128) * SP + kc + kq;
                    const float* fr1 = fr0 + 8 * SP;
                    a[m][0] = __float_as_uint(fr0[0]);
                    a[m][1] = __float_as_uint(fr1[0]);
                    a[m][2] = __float_as_uint(fr0[4]);
                    a[m][3] = __float_as_uint(fr1[4]);
                }
                const float* wr0 = wb + (kc + kq) * SPW + nq;
                const float* wr1 = wr0 + 4 * SPW;
#pragma unroll
                for (int t = 0; t < NT; ++t) {
                    uint32_t b0 = __float_as_uint(wr0[t * 8]);
                    uint32_t b1 = __float_as_uint(wr1[t * 8]);
#pragma unroll
                    for (int m = 0; m < MT; ++m)
                        mma_tf32(acc[m][t], a[m][0], a[m][1], a[m][2], a[m][3], b0, b1);
                }
            }
            __syncthreads();
        }
    }

    // -------- epilogue --------
#pragma unroll
    for (int m = 0; m < MT; ++m) {
        const int r0 = row0 + mr + m * 128;
#pragma unroll
        for (int t = 0; t < NT; ++t) {
            const int col = t * 8 + 2 * kq;
            const float s0 = sb[col],        s1 = sb[col + 1];
            const float b0 = sb[COUT + col], b1 = sb[COUT + col + 1];
#pragma unroll
            for (int h = 0; h < 2; ++h) {
                const int r = r0 + 8 * h;
                if (r >= N) continue;
                float v0 = acc[m][t][2 * h]     * s0 + b0;
                float v1 = acc[m][t][2 * h + 1] * s1 + b1;
                if (resid) {
                    float2 rr = *(const float2*)(resid + (size_t)r * ldr + col);
                    v0 += rr.x; v1 += rr.y;
                }
                v0 = fmaxf(v0, 0.f);
                v1 = fmaxf(v1, 0.f);
                if (red) {
                    float4 ra = *(const float4*)(red + (size_t)r * ldred + 2 * col);
                    v0 += ra.x + ra.y;
                    v1 += ra.z + ra.w;
                }
                *(float2*)(out + (size_t)r * ldo + col) = make_float2(v0, v1);
                if (outs)
                    *(float2*)(outs + (size_t)r * ldo + col) =
                        make_float2(__uint_as_float(tf32(v0)), __uint_as_float(tf32(v1)));
            }
        }
    }
}

template <int CIN, int COUT>
static void conv_launch(const float* feat, int ldf,
                        const int* nbrT, int NP,
                        const float* W, const float* sb,
                        const float* resid, int ldr,
                        const float* red, int ldred,
                        float* out, int ldo, float* outs, int N)
{
    constexpr int SM = SpCfg<CIN, COUT>::SMEM_BYTES;
    cudaFuncSetAttribute(spconv_mma<CIN, COUT>,
                         cudaFuncAttributeMaxDynamicSharedMemorySize, SM);
    const int grid = (N + 255) / 256;
    spconv_mma<CIN, COUT><<<grid, 256, SM>>>(
        feat, ldf, nbrT, NP, W, sb, resid, ldr, red, ldred, out, ldo, outs, N);
}

extern "C" void kernel_launch(void* const* d_in, const int* in_sizes, int n_in,
                              void* d_out, int out_size)
{
    const float* voxel  = (const float*)d_in[0];
    const float* Win    = (const float*)d_in[1];
    const float* W32    = (const float*)d_in[2];
    const float* W64    = (const float*)d_in[3];
    const float* Wd3    = (const float*)d_in[4];
    const float* W6432  = (const float*)d_in[5];
    const float* W12864 = (const float*)d_in[6];
    const float* bn32   = (const float*)d_in[7];
    const float* bn64   = (const float*)d_in[8];
    const int* nbr1  = (const int*)d_in[9];
    const int* nbr2  = (const int*)d_in[10];
    const int* nbr3  = (const int*)d_in[11];
    const int* nbr4  = (const int*)d_in[12];
    const int* nbrd2 = (const int*)d_in[13];
    const int* nbrd3 = (const int*)d_in[14];
    const int* nbrd4 = (const int*)d_in[15];
    const int* nbri4 = (const int*)d_in[16];
    const int* nbri3 = (const int*)d_in[17];
    const int* nbri2 = (const int*)d_in[18];

    const int N1 = in_sizes[9]  / 27;
    const int N2 = in_sizes[10] / 27;
    const int N3 = in_sizes[11] / 27;
    const int N4 = in_sizes[12] / 27;
    const int NP1 = (N1 + 255) & ~255;
    const int NP2 = (N2 + 255) & ~255;
    const int NP3 = (N3 + 255) & ~255;
    const int NP4 = (N4 + 255) & ~255;

    float* pool = nullptr;
    cudaGetSymbolAddress((void**)&pool, g_pool);

    size_t o = 0;
    auto take = [&](size_t n) { size_t r = o; o += (n + 255) & ~(size_t)255; return r; };

    // ---- tf32 weight copies ----
    const int nWin    = 27 * 4 * 32;
    const int nW32    = 10 * 27 * 32 * 32;
    const int nW64    = 10 * 27 * 64 * 64;
    const int nWd3    = 27 * 32 * 64;
    const int nW6432  = 3 * 27 * 64 * 32;
    const int nW12864 = 2 * 27 * 128 * 64;
    float* cWin    = pool + take(nWin);
    float* cW32    = pool + take(nW32);
    float* cW64    = pool + take(nW64);
    float* cWd3    = pool + take(nWd3);
    float* cW6432  = pool + take(nW6432);
    float* cW12864 = pool + take(nW12864);
    float* voxs    = pool + take((size_t)N1 * 4);

    // ---- transposed neighbor tables ----
    auto takeI = [&](size_t n) { return (int*)(pool + take(n)); };
    int* tn1  = takeI(27u * NP1);
    int* tn2  = takeI(27u * NP2);
    int* tn3  = takeI(27u * NP3);
    int* tn4  = takeI(27u * NP4);
    int* tnd2 = takeI(27u * NP2);
    int* tnd3 = takeI(27u * NP3);
    int* tnd4 = takeI(27u * NP4);
    int* tni4 = takeI(27u * NP3);
    int* tni3 = takeI(27u * NP2);
    int* tni2 = takeI(27u * NP1);

    // ---- feature buffers: fp32 + tf32 shadow ----
    auto buf2 = [&](size_t n, float*& b, float*& s) {
        b = pool + take(n); s = pool + take(n);
    };
    float *A, *As, *X1, *X1s, *cat1, *cat1s;
    float *C, *Cs, *Dm, *Dms, *X2, *X2s, *cat2, *cat2s;
    float *Fm, *Fms, *G, *Gs, *X3, *X3s, *cat3, *cat3s;
    float *I, *Is, *J, *Js, *cat4, *cat4s;
    buf2((size_t)N1 * 32, A, As);
    buf2((size_t)N1 * 32, X1, X1s);
    buf2((size_t)N1 * 64, cat1, cat1s);
    buf2((size_t)N2 * 32, C, Cs);
    buf2((size_t)N2 * 32, Dm, Dms);
    buf2((size_t)N2 * 32, X2, X2s);
    buf2((size_t)N2 * 64, cat2, cat2s);
    buf2((size_t)N3 * 64, Fm, Fms);
    buf2((size_t)N3 * 64, G, Gs);
    buf2((size_t)N3 * 64, X3, X3s);
    buf2((size_t)N3 * 128, cat3, cat3s);
    buf2((size_t)N4 * 64, I, Is);
    buf2((size_t)N4 * 64, J, Js);
    buf2((size_t)N4 * 128, cat4, cat4s);

    float* outp = (float*)d_out;

    // ---- prologue ----
    auto cvt = [&](const float* in, float* out, int n) {
        cvt_tf32_kernel<<<(n + 255) / 256, 256>>>(in, out, n);
    };
    cvt(Win, cWin, nWin);
    cvt(W32, cW32, nW32);
    cvt(W64, cW64, nW64);
    cvt(Wd3, cWd3, nWd3);
    cvt(W6432, cW6432, nW6432);
    cvt(W12864, cW12864, nW12864);
    cvt(voxel, voxs, N1 * 4);

    auto tr = [&](const int* nbr, int* nbrT, int N, int NP) {
        long long total = 27LL * NP;
        int grid = (int)((total + 255) / 256);
        if (grid > 16384) grid = 16384;
        transpose_nbr_kernel<<<grid, 256>>>(nbr, nbrT, N, NP);
    };
    tr(nbr1, tn1, N1, NP1);   tr(nbr2, tn2, N2, NP2);
    tr(nbr3, tn3, N3, NP3);   tr(nbr4, tn4, N4, NP4);
    tr(nbrd2, tnd2, N2, NP2); tr(nbrd3, tnd3, N3, NP3);
    tr(nbrd4, tnd4, N4, NP4); tr(nbri4, tni4, N3, NP3);
    tr(nbri3, tni3, N2, NP2); tr(nbri2, tni2, N1, NP1);

    const size_t S32   = 27u * 32 * 32;
    const size_t S64   = 27u * 64 * 64;
    const size_t S6432 = 27u * 64 * 32;
    const size_t S1286 = 27u * 128 * 64;

    // ---- Encoder ----
    conv_launch<4, 32>(voxs, 4, tn1, NP1, cWin, bn32 + 0 * 64, nullptr, 0, nullptr, 0, A, 32, As, N1);
    conv_launch<32, 32>(As, 32, tn1, NP1, cW32 + 0 * S32, bn32 + 1 * 64, nullptr, 0, nullptr, 0, X1, 32, X1s, N1);
    conv_launch<32, 32>(X1s, 32, tnd2, NP2, cW32 + 1 * S32, bn32 + 2 * 64, nullptr, 0, nullptr, 0, C, 32, Cs, N2);
    conv_launch<32, 32>(Cs, 32, tn2, NP2, cW32 + 2 * S32, bn32 + 3 * 64, nullptr, 0, nullptr, 0, Dm, 32, Dms, N2);
    conv_launch<32, 32>(Dms, 32, tn2, NP2, cW32 + 3 * S32, bn32 + 4 * 64, nullptr, 0, nullptr, 0, X2, 32, X2s, N2);
    conv_launch<32, 64>(X2s, 32, tnd3, NP3, cWd3, bn64 + 0 * 128, nullptr, 0, nullptr, 0, Fm, 64, Fms, N3);
    conv_launch<64, 64>(Fms, 64, tn3, NP3, cW64 + 0 * S64, bn64 + 1 * 128, nullptr, 0, nullptr, 0, G, 64, Gs, N3);
    conv_launch<64, 64>(Gs, 64, tn3, NP3, cW64 + 1 * S64, bn64 + 2 * 128, nullptr, 0, nullptr, 0, X3, 64, X3s, N3);
    conv_launch<64, 64>(X3s, 64, tnd4, NP4, cW64 + 2 * S64, bn64 + 3 * 128, nullptr, 0, nullptr, 0, I, 64, Is, N4);
    conv_launch<64, 64>(Is, 64, tn4, NP4, cW64 + 3 * S64, bn64 + 4 * 128, nullptr, 0, nullptr, 0, J, 64, Js, N4);
    conv_launch<64, 64>(Js, 64, tn4, NP4, cW64 + 4 * S64, bn64 + 5 * 128, nullptr, 0, nullptr, 0, cat4, 128, cat4s, N4);

    // ---- Bottleneck ----
    conv_launch<64, 64>(cat4s, 128, tn4, NP4, cW64 + 5 * S64, bn64 + 6 * 128, nullptr, 0, nullptr, 0, I, 64, Is, N4);
    conv_launch<64, 64>(Is, 64, tn4, NP4, cW64 + 6 * S64, bn64 + 7 * 128, cat4, 128, nullptr, 0, cat4 + 64, 128, cat4s + 64, N4);
    conv_launch<128, 64>(cat4s, 128, tn4, NP4, cW12864 + 0 * S1286, bn64 + 11 * 128, nullptr, 0, cat4, 128, J, 64, Js, N4);

    // ---- Decoder level 3 ----
    conv_launch<64, 64>(Js, 64, tni4, NP3, cW64 + 7 * S64, bn64 + 8 * 128, nullptr, 0, nullptr, 0, cat3, 128, cat3s, N3);
    conv_launch<64, 64>(X3s, 64, tn3, NP3, cW64 + 8 * S64, bn64 + 9 * 128, nullptr, 0, nullptr, 0, Fm, 64, Fms, N3);
    conv_launch<64, 64>(Fms, 64, tn3, NP3, cW64 + 9 * S64, bn64 + 10 * 128, X3, 64, nullptr, 0, cat3 + 64, 128, cat3s + 64, N3);
    conv_launch<128, 64>(cat3s, 128, tn3, NP3, cW12864 + 1 * S1286, bn64 + 12 * 128, nullptr, 0, cat3, 128, G, 64, Gs, N3);

    // ---- Decoder level 2 ----
    conv_launch<64, 32>(Gs, 64, tni3, NP2, cW6432 + 0 * S6432, bn32 + 11 * 64, nullptr, 0, nullptr, 0, cat2, 64, cat2s, N2);
    conv_launch<32, 32>(X2s, 32, tn2, NP2, cW32 + 4 * S32, bn32 + 5 * 64, nullptr, 0, nullptr, 0, C, 32, Cs, N2);
    conv_launch<32, 32>(Cs, 32, tn2, NP2, cW32 + 5 * S32, bn32 + 6 * 64, X2, 32, nullptr, 0, cat2 + 32, 64, cat2s + 32, N2);
    conv_launch<64, 32>(cat2s, 64, tn2, NP2, cW6432 + 1 * S6432, bn32 + 12 * 64, nullptr, 0, cat2, 64, Dm, 32, Dms, N2);

    // ---- Decoder level 1 ----
    conv_launch<32, 32>(Dms, 32, tni2, NP1, cW32 + 6 * S32, bn32 + 7 * 64, nullptr, 0, nullptr, 0, cat1, 64, cat1s, N1);
    conv_launch<32, 32>(X1s, 32, tn1, NP1, cW32 + 7 * S32, bn32 + 8 * 64, nullptr, 0, nullptr, 0, A, 32, As, N1);
    conv_launch<32, 32>(As, 32, tn1, NP1, cW32 + 8 * S32, bn32 + 9 * 64, X1, 32, nullptr, 0, cat1 + 32, 64, cat1s + 32, N1);
    conv_launch<64, 32>(cat1s, 64, tn1, NP1, cW6432 + 2 * S6432, bn32 + 13 * 64, nullptr, 0, cat1, 64, A, 32, As, N1);

    // ---- Head ----
    conv_launch<32, 32>(As, 32, tn1, NP1, cW32 + 9 * S32, bn32 + 10 * 64, nullptr, 0, nullptr, 0, outp, 32, nullptr, N1);
}

// round 9
// speedup vs baseline: 1.0852x; 1.0852x over previous
#include <cuda_runtime.h>
#include <cstddef>
#include <cstdint>

// ---------------------------------------------------------------------------
// Sparse 3D UNet forward.  cp.async double-buffered sparse-conv GEMM with
// tf32 mma.sync.m16n8k8.  R9 = R7 geometry (BM=128, 1 m-tile/warp) +
// transposed neighbor tables (coalesced khit, no snbr smem staging).
// ---------------------------------------------------------------------------

__device__ float g_pool[224u * 1024u * 1024u];   // 896 MB scratch (static: legal)

__device__ __forceinline__ void cp_async16(uint32_t dst, const void* src, int nbytes) {
    asm volatile("cp.async.cg.shared.global [%0], [%1], 16, %2;"
                 :: "r"(dst), "l"(src), "r"(nbytes));
}
__device__ __forceinline__ void cp_commit() {
    asm volatile("cp.async.commit_group;");
}
template <int NG> __device__ __forceinline__ void cp_wait() {
    asm volatile("cp.async.wait_group %0;" :: "n"(NG));
}
__device__ __forceinline__ uint32_t tf32(float x) {
    uint32_t r; asm("cvt.rna.tf32.f32 %0, %1;" : "=r"(r) : "f"(x)); return r;
}
__device__ __forceinline__ void mma_tf32(float c[4], uint32_t a0, uint32_t a1,
                                         uint32_t a2, uint32_t a3,
                                         uint32_t b0, uint32_t b1) {
    asm volatile(
        "mma.sync.aligned.m16n8k8.row.col.f32.tf32.tf32.f32 "
        "{%0,%1,%2,%3},{%4,%5,%6,%7},{%8,%9},{%0,%1,%2,%3};"
        : "+f"(c[0]), "+f"(c[1]), "+f"(c[2]), "+f"(c[3])
        : "r"(a0), "r"(a1), "r"(a2), "r"(a3), "r"(b0), "r"(b1));
}

// fp32 -> tf32-rounded fp32 bits (grid-stride)
__global__ void cvt_tf32_kernel(const float* __restrict__ in,
                                float* __restrict__ out, int n) {
    for (int i = blockIdx.x * blockDim.x + threadIdx.x; i < n;
         i += gridDim.x * blockDim.x)
        out[i] = __uint_as_float(tf32(in[i]));
}

// nbr[row][k] -> nbrT[k][row] (rows padded to NP with -1)
__global__ void transpose_nbr_kernel(const int* __restrict__ nbr,
                                     int* __restrict__ nbrT, int N, int NP) {
    const long long total = 27LL * NP;
    for (long long i = blockIdx.x * (long long)blockDim.x + threadIdx.x;
         i < total; i += gridDim.x * (long long)blockDim.x) {
        int r = (int)(i / 27), k = (int)(i - 27LL * r);
        nbrT[(size_t)k * NP + r] = (r < N) ? nbr[(size_t)r * 27 + k] : -1;
    }
}

template <int CIN, int COUT>
struct SpCfg {
    static constexpr int BM  = 128;
    static constexpr int CK  = (CIN < 32) ? CIN : 32;
    static constexpr int CK8 = (CK < 8) ? 8 : CK;
    static constexpr int NCH = CIN / CK;
    static constexpr int SP  = CK8 + 4;
    static constexpr int SPW = COUT + 8;
    static constexpr int VR  = CK / 4;
    static constexpr int NT  = COUT / 8;
    static constexpr int KS  = CK8 / 8;
    static constexpr int SMEM_BYTES = (2 * BM * SP + 2 * CK8 * SPW) * 4;
};

template <int CIN, int COUT>
__global__ void __launch_bounds__(256)
spconv_mma(const float* __restrict__ feat, int ldf,   // tf32 input
           const int* __restrict__ nbrT, int NP,      // [27][NP]
           const float* __restrict__ W,               // tf32 (27,CIN,COUT)
           const float* __restrict__ sb,
           const float* __restrict__ resid, int ldr,
           const float* __restrict__ red,   int ldred,
           float* __restrict__ out, int ldo,
           float* __restrict__ outs,                  // tf32 shadow (or null)
           int N)
{
    using C = SpCfg<CIN, COUT>;
    constexpr int BM = C::BM, CK = C::CK, CK8 = C::CK8, NCH = C::NCH;
    constexpr int SP = C::SP, SPW = C::SPW, VR = C::VR, NT = C::NT, KS = C::KS;

    extern __shared__ float smem[];
    float* sfeat = smem;                       // [2][BM*SP]
    float* sW    = smem + 2 * BM * SP;         // [2][CK8*SPW]
    __shared__ int klist[28];
    __shared__ int khit[27];
    __shared__ int knp;

    const uint32_t sfeat_sa = (uint32_t)__cvta_generic_to_shared(sfeat);
    const uint32_t sW_sa    = (uint32_t)__cvta_generic_to_shared(sW);

    const int tid  = threadIdx.x;
    const int lane = tid & 31;
    const int wid  = tid >> 5;                 // 8 warps
    const int row0 = blockIdx.x * BM;

    if (CK8 != CK) {   // zero K-pad region once (CIN=4 layer)
        for (int u = tid; u < 2 * BM * SP + 2 * CK8 * SPW; u += 256) smem[u] = 0.f;
    }

    // khit via coalesced reads of nbrT
    for (int k = wid; k < 27; k += 8) {
        const int* col = nbrT + (size_t)k * NP + row0;
        int h = (lane < BM / 4);
        if (lane < BM / 4) {
            h = 0;
#pragma unroll
            for (int j = 0; j < 4; ++j) h |= (col[lane * 4 + j] >= 0);
        }
        unsigned any = __ballot_sync(0xffffffffu, h && (lane < BM / 4));
        if (lane == 0) khit[k] = (any != 0);
    }
    __syncthreads();
    if (tid == 0) {
        int n = 0;
        for (int k = 0; k < 27; ++k) if (khit[k]) klist[n++] = k;
        knp = n;
    }
    __syncthreads();
    const int NS = knp * NCH;

    float acc[NT][4];
#pragma unroll
    for (int t = 0; t < NT; ++t)
#pragma unroll
        for (int j = 0; j < 4; ++j) acc[t][j] = 0.f;

    auto stage = [&](int s) {
        const int k  = klist[s / NCH];
        const int ch = s - (s / NCH) * NCH;
        const int kb = s & 1;
        const uint32_t fb = sfeat_sa + (uint32_t)(kb * BM * SP) * 4u;
        const int* col = nbrT + (size_t)k * NP + row0;
        for (int u = tid; u < BM * VR; u += 256) {
            int r = u / VR, v = u - r * VR;
            int idx = col[r];                       // broadcast across VR lanes
            const float* g = feat + (size_t)(idx < 0 ? 0 : idx) * ldf
                           + ch * CK + v * 4;
            cp_async16(fb + (uint32_t)(r * SP + v * 4) * 4u, g, idx < 0 ? 0 : 16);
        }
        const float* wg = W + ((size_t)k * CIN + (size_t)ch * CK) * COUT;
        const uint32_t wb = sW_sa + (uint32_t)(kb * CK8 * SPW) * 4u;
        for (int u = tid; u < CK * COUT / 4; u += 256) {
            int c = u / (COUT / 4), v = u - c * (COUT / 4);
            cp_async16(wb + (uint32_t)(c * SPW + v * 4) * 4u, wg + c * COUT + v * 4, 16);
        }
    };

    const int mrow = wid * 16 + (lane >> 2);
    const int kq   = lane & 3;
    const int nq   = lane >> 2;

    if (NS > 0) {
        stage(0);
        cp_commit();
        for (int s = 0; s < NS; ++s) {
            if (s + 1 < NS) { stage(s + 1); cp_commit(); cp_wait<1>(); }
            else            { cp_wait<0>(); }
            __syncthreads();

            const float* fb = sfeat + (s & 1) * BM * SP;
            const float* wb = sW    + (s & 1) * CK8 * SPW;
#pragma unroll
            for (int k8 = 0; k8 < KS; ++k8) {
                const int kc = k8 * 8;
                const float* fr0 = fb + mrow * SP + kc + kq;
                const float* fr1 = fr0 + 8 * SP;
                uint32_t a0 = __float_as_uint(fr0[0]);
                uint32_t a1 = __float_as_uint(fr1[0]);
                uint32_t a2 = __float_as_uint(fr0[4]);
                uint32_t a3 = __float_as_uint(fr1[4]);
                const float* wr0 = wb + (kc + kq) * SPW + nq;
                const float* wr1 = wr0 + 4 * SPW;
#pragma unroll
                for (int t = 0; t < NT; ++t) {
                    uint32_t b0 = __float_as_uint(wr0[t * 8]);
                    uint32_t b1 = __float_as_uint(wr1[t * 8]);
                    mma_tf32(acc[t], a0, a1, a2, a3, b0, b1);
                }
            }
            __syncthreads();
        }
    }

    // -------- epilogue --------
    const int r0 = row0 + mrow;
#pragma unroll
    for (int t = 0; t < NT; ++t) {
        const int col = t * 8 + 2 * kq;
        const float s0 = sb[col],        s1 = sb[col + 1];
        const float b0 = sb[COUT + col], b1 = sb[COUT + col + 1];
#pragma unroll
        for (int h = 0; h < 2; ++h) {
            const int r = r0 + 8 * h;
            if (r >= N) continue;
            float v0 = acc[t][2 * h]     * s0 + b0;
            float v1 = acc[t][2 * h + 1] * s1 + b1;
            if (resid) {
                float2 rr = *(const float2*)(resid + (size_t)r * ldr + col);
                v0 += rr.x; v1 += rr.y;
            }
            v0 = fmaxf(v0, 0.f);
            v1 = fmaxf(v1, 0.f);
            if (red) {
                float4 ra = *(const float4*)(red + (size_t)r * ldred + 2 * col);
                v0 += ra.x + ra.y;
                v1 += ra.z + ra.w;
            }
            *(float2*)(out + (size_t)r * ldo + col) = make_float2(v0, v1);
            if (outs)
                *(float2*)(outs + (size_t)r * ldo + col) =
                    make_float2(__uint_as_float(tf32(v0)), __uint_as_float(tf32(v1)));
        }
    }
}

template <int CIN, int COUT>
static void conv_launch(const float* feat, int ldf,
                        const int* nbrT, int NP,
                        const float* W, const float* sb,
                        const float* resid, int ldr,
                        const float* red, int ldred,
                        float* out, int ldo, float* outs, int N)
{
    constexpr int SM = SpCfg<CIN, COUT>::SMEM_BYTES;
    cudaFuncSetAttribute(spconv_mma<CIN, COUT>,
                         cudaFuncAttributeMaxDynamicSharedMemorySize, SM);
    const int grid = (N + 127) / 128;
    spconv_mma<CIN, COUT><<<grid, 256, SM>>>(
        feat, ldf, nbrT, NP, W, sb, resid, ldr, red, ldred, out, ldo, outs, N);
}

extern "C" void kernel_launch(void* const* d_in, const int* in_sizes, int n_in,
                              void* d_out, int out_size)
{
    const float* voxel  = (const float*)d_in[0];
    const float* Win    = (const float*)d_in[1];
    const float* W32    = (const float*)d_in[2];
    const float* W64    = (const float*)d_in[3];
    const float* Wd3    = (const float*)d_in[4];
    const float* W6432  = (const float*)d_in[5];
    const float* W12864 = (const float*)d_in[6];
    const float* bn32   = (const float*)d_in[7];
    const float* bn64   = (const float*)d_in[8];
    const int* nbr1  = (const int*)d_in[9];
    const int* nbr2  = (const int*)d_in[10];
    const int* nbr3  = (const int*)d_in[11];
    const int* nbr4  = (const int*)d_in[12];
    const int* nbrd2 = (const int*)d_in[13];
    const int* nbrd3 = (const int*)d_in[14];
    const int* nbrd4 = (const int*)d_in[15];
    const int* nbri4 = (const int*)d_in[16];
    const int* nbri3 = (const int*)d_in[17];
    const int* nbri2 = (const int*)d_in[18];

    const int N1 = in_sizes[9]  / 27;
    const int N2 = in_sizes[10] / 27;
    const int N3 = in_sizes[11] / 27;
    const int N4 = in_sizes[12] / 27;
    const int NP1 = (N1 + 127) & ~127;
    const int NP2 = (N2 + 127) & ~127;
    const int NP3 = (N3 + 127) & ~127;
    const int NP4 = (N4 + 127) & ~127;

    float* pool = nullptr;
    cudaGetSymbolAddress((void**)&pool, g_pool);

    size_t o = 0;
    auto take = [&](size_t n) { size_t r = o; o += (n + 255) & ~(size_t)255; return r; };

    // ---- tf32 weight copies ----
    const int nWin    = 27 * 4 * 32;
    const int nW32    = 10 * 27 * 32 * 32;
    const int nW64    = 10 * 27 * 64 * 64;
    const int nWd3    = 27 * 32 * 64;
    const int nW6432  = 3 * 27 * 64 * 32;
    const int nW12864 = 2 * 27 * 128 * 64;
    float* cWin    = pool + take(nWin);
    float* cW32    = pool + take(nW32);
    float* cW64    = pool + take(nW64);
    float* cWd3    = pool + take(nWd3);
    float* cW6432  = pool + take(nW6432);
    float* cW12864 = pool + take(nW12864);
    float* voxs    = pool + take((size_t)N1 * 4);

    // ---- transposed neighbor tables ----
    auto takeI = [&](size_t n) { return (int*)(pool + take(n)); };
    int* tn1  = takeI(27u * NP1);
    int* tn2  = takeI(27u * NP2);
    int* tn3  = takeI(27u * NP3);
    int* tn4  = takeI(27u * NP4);
    int* tnd2 = takeI(27u * NP2);
    int* tnd3 = takeI(27u * NP3);
    int* tnd4 = takeI(27u * NP4);
    int* tni4 = takeI(27u * NP3);
    int* tni3 = takeI(27u * NP2);
    int* tni2 = takeI(27u * NP1);

    // ---- feature buffers: fp32 + tf32 shadow ----
    auto buf2 = [&](size_t n, float*& b, float*& s) {
        b = pool + take(n); s = pool + take(n);
    };
    float *A, *As, *X1, *X1s, *cat1, *cat1s;
    float *C, *Cs, *Dm, *Dms, *X2, *X2s, *cat2, *cat2s;
    float *Fm, *Fms, *G, *Gs, *X3, *X3s, *cat3, *cat3s;
    float *I, *Is, *J, *Js, *cat4, *cat4s;
    buf2((size_t)N1 * 32, A, As);
    buf2((size_t)N1 * 32, X1, X1s);
    buf2((size_t)N1 * 64, cat1, cat1s);
    buf2((size_t)N2 * 32, C, Cs);
    buf2((size_t)N2 * 32, Dm, Dms);
    buf2((size_t)N2 * 32, X2, X2s);
    buf2((size_t)N2 * 64, cat2, cat2s);
    buf2((size_t)N3 * 64, Fm, Fms);
    buf2((size_t)N3 * 64, G, Gs);
    buf2((size_t)N3 * 64, X3, X3s);
    buf2((size_t)N3 * 128, cat3, cat3s);
    buf2((size_t)N4 * 64, I, Is);
    buf2((size_t)N4 * 64, J, Js);
    buf2((size_t)N4 * 128, cat4, cat4s);

    float* outp = (float*)d_out;

    // ---- prologue ----
    auto cvt = [&](const float* in, float* out, int n) {
        cvt_tf32_kernel<<<(n + 255) / 256, 256>>>(in, out, n);
    };
    cvt(Win, cWin, nWin);
    cvt(W32, cW32, nW32);
    cvt(W64, cW64, nW64);
    cvt(Wd3, cWd3, nWd3);
    cvt(W6432, cW6432, nW6432);
    cvt(W12864, cW12864, nW12864);
    cvt(voxel, voxs, N1 * 4);

    auto tr = [&](const int* nbr, int* nbrT, int N, int NP) {
        long long total = 27LL * NP;
        int grid = (int)((total + 255) / 256);
        if (grid > 16384) grid = 16384;
        transpose_nbr_kernel<<<grid, 256>>>(nbr, nbrT, N, NP);
    };
    tr(nbr1, tn1, N1, NP1);   tr(nbr2, tn2, N2, NP2);
    tr(nbr3, tn3, N3, NP3);   tr(nbr4, tn4, N4, NP4);
    tr(nbrd2, tnd2, N2, NP2); tr(nbrd3, tnd3, N3, NP3);
    tr(nbrd4, tnd4, N4, NP4); tr(nbri4, tni4, N3, NP3);
    tr(nbri3, tni3, N2, NP2); tr(nbri2, tni2, N1, NP1);

    const size_t S32   = 27u * 32 * 32;
    const size_t S64   = 27u * 64 * 64;
    const size_t S6432 = 27u * 64 * 32;
    const size_t S1286 = 27u * 128 * 64;

    // ---- Encoder ----
    conv_launch<4, 32>(voxs, 4, tn1, NP1, cWin, bn32 + 0 * 64, nullptr, 0, nullptr, 0, A, 32, As, N1);
    conv_launch<32, 32>(As, 32, tn1, NP1, cW32 + 0 * S32, bn32 + 1 * 64, nullptr, 0, nullptr, 0, X1, 32, X1s, N1);
    conv_launch<32, 32>(X1s, 32, tnd2, NP2, cW32 + 1 * S32, bn32 + 2 * 64, nullptr, 0, nullptr, 0, C, 32, Cs, N2);
    conv_launch<32, 32>(Cs, 32, tn2, NP2, cW32 + 2 * S32, bn32 + 3 * 64, nullptr, 0, nullptr, 0, Dm, 32, Dms, N2);
    conv_launch<32, 32>(Dms, 32, tn2, NP2, cW32 + 3 * S32, bn32 + 4 * 64, nullptr, 0, nullptr, 0, X2, 32, X2s, N2);
    conv_launch<32, 64>(X2s, 32, tnd3, NP3, cWd3, bn64 + 0 * 128, nullptr, 0, nullptr, 0, Fm, 64, Fms, N3);
    conv_launch<64, 64>(Fms, 64, tn3, NP3, cW64 + 0 * S64, bn64 + 1 * 128, nullptr, 0, nullptr, 0, G, 64, Gs, N3);
    conv_launch<64, 64>(Gs, 64, tn3, NP3, cW64 + 1 * S64, bn64 + 2 * 128, nullptr, 0, nullptr, 0, X3, 64, X3s, N3);
    conv_launch<64, 64>(X3s, 64, tnd4, NP4, cW64 + 2 * S64, bn64 + 3 * 128, nullptr, 0, nullptr, 0, I, 64, Is, N4);
    conv_launch<64, 64>(Is, 64, tn4, NP4, cW64 + 3 * S64, bn64 + 4 * 128, nullptr, 0, nullptr, 0, J, 64, Js, N4);
    conv_launch<64, 64>(Js, 64, tn4, NP4, cW64 + 4 * S64, bn64 + 5 * 128, nullptr, 0, nullptr, 0, cat4, 128, cat4s, N4);

    // ---- Bottleneck ----
    conv_launch<64, 64>(cat4s, 128, tn4, NP4, cW64 + 5 * S64, bn64 + 6 * 128, nullptr, 0, nullptr, 0, I, 64, Is, N4);
    conv_launch<64, 64>(Is, 64, tn4, NP4, cW64 + 6 * S64, bn64 + 7 * 128, cat4, 128, nullptr, 0, cat4 + 64, 128, cat4s + 64, N4);
    conv_launch<128, 64>(cat4s, 128, tn4, NP4, cW12864 + 0 * S1286, bn64 + 11 * 128, nullptr, 0, cat4, 128, J, 64, Js, N4);

    // ---- Decoder level 3 ----
    conv_launch<64, 64>(Js, 64, tni4, NP3, cW64 + 7 * S64, bn64 + 8 * 128, nullptr, 0, nullptr, 0, cat3, 128, cat3s, N3);
    conv_launch<64, 64>(X3s, 64, tn3, NP3, cW64 + 8 * S64, bn64 + 9 * 128, nullptr, 0, nullptr, 0, Fm, 64, Fms, N3);
    conv_launch<64, 64>(Fms, 64, tn3, NP3, cW64 + 9 * S64, bn64 + 10 * 128, X3, 64, nullptr, 0, cat3 + 64, 128, cat3s + 64, N3);
    conv_launch<128, 64>(cat3s, 128, tn3, NP3, cW12864 + 1 * S1286, bn64 + 12 * 128, nullptr, 0, cat3, 128, G, 64, Gs, N3);

    // ---- Decoder level 2 ----
    conv_launch<64, 32>(Gs, 64, tni3, NP2, cW6432 + 0 * S6432, bn32 + 11 * 64, nullptr, 0, nullptr, 0, cat2, 64, cat2s, N2);
    conv_launch<32, 32>(X2s, 32, tn2, NP2, cW32 + 4 * S32, bn32 + 5 * 64, nullptr, 0, nullptr, 0, C, 32, Cs, N2);
    conv_launch<32, 32>(Cs, 32, tn2, NP2, cW32 + 5 * S32, bn32 + 6 * 64, X2, 32, nullptr, 0, cat2 + 32, 64, cat2s + 32, N2);
    conv_launch<64, 32>(cat2s, 64, tn2, NP2, cW6432 + 1 * S6432, bn32 + 12 * 64, nullptr, 0, cat2, 64, Dm, 32, Dms, N2);

    // ---- Decoder level 1 ----
    conv_launch<32, 32>(Dms, 32, tni2, NP1, cW32 + 6 * S32, bn32 + 7 * 64, nullptr, 0, nullptr, 0, cat1, 64, cat1s, N1);
    conv_launch<32, 32>(X1s, 32, tn1, NP1, cW32 + 7 * S32, bn32 + 8 * 64, nullptr, 0, nullptr, 0, A, 32, As, N1);
    conv_launch<32, 32>(As, 32, tn1, NP1, cW32 + 8 * S32, bn32 + 9 * 64, X1, 32, nullptr, 0, cat1 + 32, 64, cat1s + 32, N1);
    conv_launch<64, 32>(cat1s, 64, tn1, NP1, cW6432 + 2 * S6432, bn32 + 13 * 64, nullptr, 0, cat1, 64, A, 32, As, N1);

    // ---- Head ----
    conv_launch<32, 32>(As, 32, tn1, NP1, cW32 + 9 * S32, bn32 + 10 * 64, nullptr, 0, nullptr, 0, outp, 32, nullptr, N1);
}

// round 10
// speedup vs baseline: 1.1055x; 1.0186x over previous
#include <cuda_runtime.h>
#include <cstddef>
#include <cstdint>

// ---------------------------------------------------------------------------
// Sparse 3D UNet forward.  cp.async double-buffered sparse-conv GEMM with
// tf32 mma.sync.m16n8k8.  R10 = R7 baseline (BM=128, snbr in smem) +
// weights pre-packed in MMA B-fragment order so the inner loop reads B via
// LDS128 (2 loads for COUT=32 / 4 for COUT=64 instead of 8/16 scalar LDS).
// ---------------------------------------------------------------------------

__device__ float g_pool[224u * 1024u * 1024u];   // 896 MB scratch (static: legal)

__device__ __forceinline__ void cp_async16(uint32_t dst, const void* src, int nbytes) {
    asm volatile("cp.async.cg.shared.global [%0], [%1], 16, %2;"
                 :: "r"(dst), "l"(src), "r"(nbytes));
}
__device__ __forceinline__ void cp_commit() {
    asm volatile("cp.async.commit_group;");
}
template <int NG> __device__ __forceinline__ void cp_wait() {
    asm volatile("cp.async.wait_group %0;" :: "n"(NG));
}
__device__ __forceinline__ uint32_t tf32(float x) {
    uint32_t r; asm("cvt.rna.tf32.f32 %0, %1;" : "=r"(r) : "f"(x)); return r;
}
__device__ __forceinline__ void mma_tf32(float c[4], uint32_t a0, uint32_t a1,
                                         uint32_t a2, uint32_t a3,
                                         uint32_t b0, uint32_t b1) {
    asm volatile(
        "mma.sync.aligned.m16n8k8.row.col.f32.tf32.tf32.f32 "
        "{%0,%1,%2,%3},{%4,%5,%6,%7},{%8,%9},{%0,%1,%2,%3};"
        : "+f"(c[0]), "+f"(c[1]), "+f"(c[2]), "+f"(c[3])
        : "r"(a0), "r"(a1), "r"(a2), "r"(a3), "r"(b0), "r"(b1));
}

// fp32 -> tf32-rounded fp32 bits (grid-stride); used for the voxel input.
__global__ void cvt_tf32_kernel(const float* __restrict__ in,
                                float* __restrict__ out, int n) {
    for (int i = blockIdx.x * blockDim.x + threadIdx.x; i < n;
         i += gridDim.x * blockDim.x)
        out[i] = __uint_as_float(tf32(in[i]));
}

template <int CIN, int COUT>
struct SpCfg {
    static constexpr int BM  = 128;
    static constexpr int CK  = (CIN < 32) ? CIN : 32;   // channel chunk
    static constexpr int CK8 = (CK < 8) ? 8 : CK;       // padded K
    static constexpr int NCH = CIN / CK;
    static constexpr int SP  = CK8 + 4;                 // feat row stride
    static constexpr int VR  = CK / 4;
    static constexpr int NT  = COUT / 8;                // n-tiles per warp
    static constexpr int KS  = CK8 / 8;                 // k8 steps per stage
    static constexpr int P   = 2 * NT;                  // packed floats/lane/k8
    static constexpr int PS  = P + 4;                   // smem lane stride
    static constexpr int WSTG = KS * 32 * P;            // packed floats / stage (gmem)
    static constexpr int WSMS = KS * 32 * PS;           // packed floats / stage (smem)
    static constexpr int SMEM_BYTES =
        (2 * BM * SP + 2 * WSMS) * 4 + 27 * BM * 4 + 64 * 4;
    static constexpr int PACKED_PER_LAYER = 27 * NCH * WSTG;
};

// Pack W (27, CIN, COUT) into B-fragment order, tf32-rounded, zero-filled pad.
// Layout: [k][ch][k8][lane][p] with p = 2t+j,
//   value = W[k][ch*CK + k8*8 + (lane&3) + 4j][t*8 + (lane>>2)]
template <int CIN, int COUT>
__global__ void pack_w_kernel(const float* __restrict__ W, float* __restrict__ Wp) {
    using C = SpCfg<CIN, COUT>;
    const int total = C::PACKED_PER_LAYER;
    for (int o = blockIdx.x * blockDim.x + threadIdx.x; o < total;
         o += gridDim.x * blockDim.x) {
        int p = o % C::P;
        int rest = o / C::P;
        int ln = rest % 32; rest /= 32;
        int k8 = rest % C::KS; rest /= C::KS;
        int ch = rest % C::NCH;
        int k  = rest / C::NCH;
        int kq = ln & 3, nq = ln >> 2;
        int t = p >> 1, j = p & 1;
        int rk  = k8 * 8 + kq + 4 * j;       // row within chunk (may exceed CK)
        int col = t * 8 + nq;
        float v = 0.f;
        if (rk < C::CK)
            v = W[((size_t)k * CIN + ch * C::CK + rk) * COUT + col];
        Wp[o] = __uint_as_float(tf32(v));
    }
}

template <int CIN, int COUT>
__global__ void __launch_bounds__(256)
spconv_mma(const float* __restrict__ feat, int ldf,   // tf32 input
           const int* __restrict__ nbr,
           const float* __restrict__ Wp,              // packed tf32 weights
           const float* __restrict__ sb,
           const float* __restrict__ resid, int ldr,
           const float* __restrict__ red,   int ldred,
           float* __restrict__ out, int ldo,
           float* __restrict__ outs,                  // tf32 shadow (or null)
           int N)
{
    using C = SpCfg<CIN, COUT>;
    constexpr int BM = C::BM, CK = C::CK, CK8 = C::CK8, NCH = C::NCH;
    constexpr int SP = C::SP, VR = C::VR, NT = C::NT, KS = C::KS;
    constexpr int P = C::P, PS = C::PS, WSTG = C::WSTG, WSMS = C::WSMS;

    extern __shared__ float smem[];
    float* sfeat = smem;                              // [2][BM*SP]
    float* sW    = smem + 2 * BM * SP;                // [2][WSMS]
    int*   snbr  = (int*)(sW + 2 * WSMS);             // [27*BM]
    int*   kmeta = snbr + 27 * BM;
    int*   khit  = kmeta;
    int*   klist = kmeta + 27;
    int*   knp   = kmeta + 54;

    const uint32_t sfeat_sa = (uint32_t)__cvta_generic_to_shared(sfeat);
    const uint32_t sW_sa    = (uint32_t)__cvta_generic_to_shared(sW);

    const int tid  = threadIdx.x;
    const int lane = tid & 31;
    const int wid  = tid >> 5;             // 8 warps
    const int row0 = blockIdx.x * BM;

    // Zero feature pad region once when K is padded (CIN=4 layer)
    if (CK8 != CK) {
        for (int u = tid; u < 2 * BM * SP; u += 256) smem[u] = 0.f;
    }

    // Stage neighbor indices
    for (int e = tid; e < BM * 27; e += 256) {
        int r = e / 27, k = e - r * 27;
        int g = row0 + r;
        snbr[k * BM + r] = (g < N) ? nbr[(size_t)g * 27 + k] : -1;
    }
    __syncthreads();
    if (tid < 27) {
        int h = 0;
        for (int r = 0; r < BM && !h; ++r) h = (snbr[tid * BM + r] >= 0);
        khit[tid] = h;
    }
    __syncthreads();
    if (tid == 0) {
        int n = 0;
        for (int k = 0; k < 27; ++k) if (khit[k]) klist[n++] = k;
        *knp = n;
    }
    __syncthreads();
    const int NS = (*knp) * NCH;

    float acc[NT][4];
#pragma unroll
    for (int t = 0; t < NT; ++t)
#pragma unroll
        for (int j = 0; j < 4; ++j) acc[t][j] = 0.f;

    auto stage = [&](int s) {
        const int k  = klist[s / NCH];
        const int ch = s - (s / NCH) * NCH;
        const int kb = s & 1;
        const uint32_t fb = sfeat_sa + (uint32_t)(kb * BM * SP) * 4u;
        for (int u = tid; u < BM * VR; u += 256) {
            int r = u / VR, v = u - r * VR;
            int idx = snbr[k * BM + r];
            const float* g = feat + (size_t)(idx < 0 ? 0 : idx) * ldf
                           + ch * CK + v * 4;
            cp_async16(fb + (uint32_t)(r * SP + v * 4) * 4u, g, idx < 0 ? 0 : 16);
        }
        // packed weight tile for this (k, ch)
        const float* wg = Wp + (size_t)(k * NCH + ch) * WSTG;
        const uint32_t wb = sW_sa + (uint32_t)(kb * WSMS) * 4u;
        for (int u = tid; u < WSTG / 4; u += 256) {
            int ln8 = u / (P / 4);            // combined k8*32 + lane
            int c   = u - ln8 * (P / 4);
            cp_async16(wb + (uint32_t)(ln8 * PS + 4 * c) * 4u,
                       wg + ln8 * P + 4 * c, 16);
        }
    };

    const int mrow = wid * 16 + (lane >> 2);
    const int kq   = lane & 3;

    if (NS > 0) {
        stage(0);
        cp_commit();
        for (int s = 0; s < NS; ++s) {
            if (s + 1 < NS) { stage(s + 1); cp_commit(); cp_wait<1>(); }
            else            { cp_wait<0>(); }
            __syncthreads();

            const float* fb = sfeat + (s & 1) * BM * SP;
            const float* wb = sW    + (s & 1) * WSMS;
#pragma unroll
            for (int k8 = 0; k8 < KS; ++k8) {
                const int kc = k8 * 8;
                const float* fr0 = fb + mrow * SP + kc + kq;
                const float* fr1 = fr0 + 8 * SP;
                uint32_t a0 = __float_as_uint(fr0[0]);
                uint32_t a1 = __float_as_uint(fr1[0]);
                uint32_t a2 = __float_as_uint(fr0[4]);
                uint32_t a3 = __float_as_uint(fr1[4]);
                const float* wrow = wb + (k8 * 32 + lane) * PS;
                float barr[P];
#pragma unroll
                for (int c = 0; c < P / 4; ++c)
                    *(float4*)(barr + 4 * c) = *(const float4*)(wrow + 4 * c);
#pragma unroll
                for (int t = 0; t < NT; ++t)
                    mma_tf32(acc[t], a0, a1, a2, a3,
                             __float_as_uint(barr[2 * t]),
                             __float_as_uint(barr[2 * t + 1]));
            }
            __syncthreads();
        }
    }

    // -------- epilogue --------
    const int r0 = row0 + mrow;
#pragma unroll
    for (int t = 0; t < NT; ++t) {
        const int col = t * 8 + 2 * kq;
        const float s0 = sb[col],        s1 = sb[col + 1];
        const float b0 = sb[COUT + col], b1 = sb[COUT + col + 1];
#pragma unroll
        for (int h = 0; h < 2; ++h) {
            const int r = r0 + 8 * h;
            if (r >= N) continue;
            float v0 = acc[t][2 * h]     * s0 + b0;
            float v1 = acc[t][2 * h + 1] * s1 + b1;
            if (resid) {
                float2 rr = *(const float2*)(resid + (size_t)r * ldr + col);
                v0 += rr.x; v1 += rr.y;
            }
            v0 = fmaxf(v0, 0.f);
            v1 = fmaxf(v1, 0.f);
            if (red) {
                float4 ra = *(const float4*)(red + (size_t)r * ldred + 2 * col);
                v0 += ra.x + ra.y;
                v1 += ra.z + ra.w;
            }
            *(float2*)(out + (size_t)r * ldo + col) = make_float2(v0, v1);
            if (outs)
                *(float2*)(outs + (size_t)r * ldo + col) =
                    make_float2(__uint_as_float(tf32(v0)), __uint_as_float(tf32(v1)));
        }
    }
}

template <int CIN, int COUT>
static void conv_launch(const float* feat, int ldf, const int* nbr,
                        const float* Wp, const float* sb,
                        const float* resid, int ldr,
                        const float* red, int ldred,
                        float* out, int ldo, float* outs, int N)
{
    constexpr int SM = SpCfg<CIN, COUT>::SMEM_BYTES;
    cudaFuncSetAttribute(spconv_mma<CIN, COUT>,
                         cudaFuncAttributeMaxDynamicSharedMemorySize, SM);
    const int grid = (N + 127) / 128;
    spconv_mma<CIN, COUT><<<grid, 256, SM>>>(
        feat, ldf, nbr, Wp, sb, resid, ldr, red, ldred, out, ldo, outs, N);
}

template <int CIN, int COUT>
static void pack_launch(const float* W, float* Wp, int layers)
{
    constexpr int per = SpCfg<CIN, COUT>::PACKED_PER_LAYER;
    const size_t src_per = 27u * CIN * COUT;
    for (int l = 0; l < layers; ++l)
        pack_w_kernel<CIN, COUT><<<(per + 255) / 256, 256>>>(
            W + (size_t)l * src_per, Wp + (size_t)l * per);
}

extern "C" void kernel_launch(void* const* d_in, const int* in_sizes, int n_in,
                              void* d_out, int out_size)
{
    const float* voxel  = (const float*)d_in[0];
    const float* Win    = (const float*)d_in[1];
    const float* W32    = (const float*)d_in[2];
    const float* W64    = (const float*)d_in[3];
    const float* Wd3    = (const float*)d_in[4];
    const float* W6432  = (const float*)d_in[5];
    const float* W12864 = (const float*)d_in[6];
    const float* bn32   = (const float*)d_in[7];
    const float* bn64   = (const float*)d_in[8];
    const int* nbr1  = (const int*)d_in[9];
    const int* nbr2  = (const int*)d_in[10];
    const int* nbr3  = (const int*)d_in[11];
    const int* nbr4  = (const int*)d_in[12];
    const int* nbrd2 = (const int*)d_in[13];
    const int* nbrd3 = (const int*)d_in[14];
    const int* nbrd4 = (const int*)d_in[15];
    const int* nbri4 = (const int*)d_in[16];
    const int* nbri3 = (const int*)d_in[17];
    const int* nbri2 = (const int*)d_in[18];

    const int N1 = in_sizes[9]  / 27;
    const int N2 = in_sizes[10] / 27;
    const int N3 = in_sizes[11] / 27;
    const int N4 = in_sizes[12] / 27;

    float* pool = nullptr;
    cudaGetSymbolAddress((void**)&pool, g_pool);

    size_t o = 0;
    auto take = [&](size_t n) { size_t r = o; o += (n + 255) & ~(size_t)255; return r; };

    // ---- packed tf32 weights ----
    constexpr int Pin    = SpCfg<4, 32>::PACKED_PER_LAYER;
    constexpr int P32    = SpCfg<32, 32>::PACKED_PER_LAYER;
    constexpr int P64    = SpCfg<64, 64>::PACKED_PER_LAYER;
    constexpr int Pd3    = SpCfg<32, 64>::PACKED_PER_LAYER;
    constexpr int P6432  = SpCfg<64, 32>::PACKED_PER_LAYER;
    constexpr int P12864 = SpCfg<128, 64>::PACKED_PER_LAYER;
    float* pWin    = pool + take(Pin);
    float* pW32    = pool + take((size_t)10 * P32);
    float* pW64    = pool + take((size_t)10 * P64);
    float* pWd3    = pool + take(Pd3);
    float* pW6432  = pool + take((size_t)3 * P6432);
    float* pW12864 = pool + take((size_t)2 * P12864);
    float* voxs    = pool + take((size_t)N1 * 4);

    // ---- feature buffers: fp32 + tf32 shadow ----
    auto buf2 = [&](size_t n, float*& b, float*& s) {
        b = pool + take(n); s = pool + take(n);
    };
    float *A, *As, *X1, *X1s, *cat1, *cat1s;
    float *C, *Cs, *Dm, *Dms, *X2, *X2s, *cat2, *cat2s;
    float *Fm, *Fms, *G, *Gs, *X3, *X3s, *cat3, *cat3s;
    float *I, *Is, *J, *Js, *cat4, *cat4s;
    buf2((size_t)N1 * 32, A, As);
    buf2((size_t)N1 * 32, X1, X1s);
    buf2((size_t)N1 * 64, cat1, cat1s);
    buf2((size_t)N2 * 32, C, Cs);
    buf2((size_t)N2 * 32, Dm, Dms);
    buf2((size_t)N2 * 32, X2, X2s);
    buf2((size_t)N2 * 64, cat2, cat2s);
    buf2((size_t)N3 * 64, Fm, Fms);
    buf2((size_t)N3 * 64, G, Gs);
    buf2((size_t)N3 * 64, X3, X3s);
    buf2((size_t)N3 * 128, cat3, cat3s);
    buf2((size_t)N4 * 64, I, Is);
    buf2((size_t)N4 * 64, J, Js);
    buf2((size_t)N4 * 128, cat4, cat4s);

    float* outp = (float*)d_out;

    // ---- prologue: pack weights (tf32), convert voxel ----
    pack_launch<4, 32>(Win, pWin, 1);
    pack_launch<32, 32>(W32, pW32, 10);
    pack_launch<64, 64>(W64, pW64, 10);
    pack_launch<32, 64>(Wd3, pWd3, 1);
    pack_launch<64, 32>(W6432, pW6432, 3);
    pack_launch<128, 64>(W12864, pW12864, 2);
    cvt_tf32_kernel<<<(N1 * 4 + 255) / 256, 256>>>(voxel, voxs, N1 * 4);

    // ---- Encoder ----
    conv_launch<4, 32>(voxs, 4, nbr1, pWin, bn32 + 0 * 64, nullptr, 0, nullptr, 0, A, 32, As, N1);
    conv_launch<32, 32>(As, 32, nbr1, pW32 + 0 * (size_t)P32, bn32 + 1 * 64, nullptr, 0, nullptr, 0, X1, 32, X1s, N1);
    conv_launch<32, 32>(X1s, 32, nbrd2, pW32 + 1 * (size_t)P32, bn32 + 2 * 64, nullptr, 0, nullptr, 0, C, 32, Cs, N2);
    conv_launch<32, 32>(Cs, 32, nbr2, pW32 + 2 * (size_t)P32, bn32 + 3 * 64, nullptr, 0, nullptr, 0, Dm, 32, Dms, N2);
    conv_launch<32, 32>(Dms, 32, nbr2, pW32 + 3 * (size_t)P32, bn32 + 4 * 64, nullptr, 0, nullptr, 0, X2, 32, X2s, N2);
    conv_launch<32, 64>(X2s, 32, nbrd3, pWd3, bn64 + 0 * 128, nullptr, 0, nullptr, 0, Fm, 64, Fms, N3);
    conv_launch<64, 64>(Fms, 64, nbr3, pW64 + 0 * (size_t)P64, bn64 + 1 * 128, nullptr, 0, nullptr, 0, G, 64, Gs, N3);
    conv_launch<64, 64>(Gs, 64, nbr3, pW64 + 1 * (size_t)P64, bn64 + 2 * 128, nullptr, 0, nullptr, 0, X3, 64, X3s, N3);
    conv_launch<64, 64>(X3s, 64, nbrd4, pW64 + 2 * (size_t)P64, bn64 + 3 * 128, nullptr, 0, nullptr, 0, I, 64, Is, N4);
    conv_launch<64, 64>(Is, 64, nbr4, pW64 + 3 * (size_t)P64, bn64 + 4 * 128, nullptr, 0, nullptr, 0, J, 64, Js, N4);
    conv_launch<64, 64>(Js, 64, nbr4, pW64 + 4 * (size_t)P64, bn64 + 5 * 128, nullptr, 0, nullptr, 0, cat4, 128, cat4s, N4);

    // ---- Bottleneck ----
    conv_launch<64, 64>(cat4s, 128, nbr4, pW64 + 5 * (size_t)P64, bn64 + 6 * 128, nullptr, 0, nullptr, 0, I, 64, Is, N4);
    conv_launch<64, 64>(Is, 64, nbr4, pW64 + 6 * (size_t)P64, bn64 + 7 * 128, cat4, 128, nullptr, 0, cat4 + 64, 128, cat4s + 64, N4);
    conv_launch<128, 64>(cat4s, 128, nbr4, pW12864 + 0 * (size_t)P12864, bn64 + 11 * 128, nullptr, 0, cat4, 128, J, 64, Js, N4);

    // ---- Decoder level 3 ----
    conv_launch<64, 64>(Js, 64, nbri4, pW64 + 7 * (size_t)P64, bn64 + 8 * 128, nullptr, 0, nullptr, 0, cat3, 128, cat3s, N3);
    conv_launch<64, 64>(X3s, 64, nbr3, pW64 + 8 * (size_t)P64, bn64 + 9 * 128, nullptr, 0, nullptr, 0, Fm, 64, Fms, N3);
    conv_launch<64, 64>(Fms, 64, nbr3, pW64 + 9 * (size_t)P64, bn64 + 10 * 128, X3, 64, nullptr, 0, cat3 + 64, 128, cat3s + 64, N3);
    conv_launch<128, 64>(cat3s, 128, nbr3, pW12864 + 1 * (size_t)P12864, bn64 + 12 * 128, nullptr, 0, cat3, 128, G, 64, Gs, N3);

    // ---- Decoder level 2 ----
    conv_launch<64, 32>(Gs, 64, nbri3, pW6432 + 0 * (size_t)P6432, bn32 + 11 * 64, nullptr, 0, nullptr, 0, cat2, 64, cat2s, N2);
    conv_launch<32, 32>(X2s, 32, nbr2, pW32 + 4 * (size_t)P32, bn32 + 5 * 64, nullptr, 0, nullptr, 0, C, 32, Cs, N2);
    conv_launch<32, 32>(Cs, 32, nbr2, pW32 + 5 * (size_t)P32, bn32 + 6 * 64, X2, 32, nullptr, 0, cat2 + 32, 64, cat2s + 32, N2);
    conv_launch<64, 32>(cat2s, 64, nbr2, pW6432 + 1 * (size_t)P6432, bn32 + 12 * 64, nullptr, 0, cat2, 64, Dm, 32, Dms, N2);

    // ---- Decoder level 1 ----
    conv_launch<32, 32>(Dms, 32, nbri2, pW32 + 6 * (size_t)P32, bn32 + 7 * 64, nullptr, 0, nullptr, 0, cat1, 64, cat1s, N1);
    conv_launch<32, 32>(X1s, 32, nbr1, pW32 + 7 * (size_t)P32, bn32 + 8 * 64, nullptr, 0, nullptr, 0, A, 32, As, N1);
    conv_launch<32, 32>(As, 32, nbr1, pW32 + 8 * (size_t)P32, bn32 + 9 * 64, X1, 32, nullptr, 0, cat1 + 32, 64, cat1s + 32, N1);
    conv_launch<64, 32>(cat1s, 64, nbr1, pW6432 + 2 * (size_t)P6432, bn32 + 13 * 64, nullptr, 0, cat1, 64, A, 32, As, N1);

    // ---- Head ----
    conv_launch<32, 32>(As, 32, nbr1, pW32 + 9 * (size_t)P32, bn32 + 10 * 64, nullptr, 0, nullptr, 0, outp, 32, nullptr, N1);
}